// round 9
// baseline (speedup 1.0000x reference)
#include <cuda_runtime.h>
#include <cuda_fp16.h>
#include <math.h>

#define NB   16            // batches
#define NN   1024          // N == Mp
#define GRID 128           // 16 batches x 8 blocks; 1 CTA/SM, all co-resident
#define TPB  256
#define PB   8             // blocks per batch
#define RPW  16            // rows per warp
#define SROWS_W 10         // smem-resident K rows per warp (80/block)

// ---- dynamic smem layout (bytes) ----
#define OFF_SK   0
#define SZ_SK    (80 * 1024 * 2)        // 163840: fp16 K' for 80 rows
#define OFF_ST   (OFF_SK + SZ_SK)
#define SZ_ST    (8 * 1024 * 4)         // 32768: per-warp column partials
#define OFF_SB   (OFF_ST + SZ_ST)
#define SZ_SB    (1024 * 4)             // 4096: b vector
#define OFF_SU   (OFF_SB + SZ_SB)       // 512: u
#define OFF_SA   (OFF_SU + 512)         // 512: a
#define OFF_SR   (OFF_SA + 512)         // 1024: reduction
#define SMEM_TOTAL (OFF_SR + 1024)      // 202752

// ---- static device scratch ----
__device__ uint4  g_K4[(size_t)NB * NN * NN / 8];   // fp16 K' (only rows r>=10 used)
__device__ float  g_part[2][NB][PB][NN];
__device__ float  g_errpart[2][GRID];
__device__ float  g_costpart[GRID];
__device__ int          g_cnt;
__device__ volatile int g_gen;

// ---- packed f32x2 helpers (Blackwell FFMA2 — PTX only) ----
__device__ __forceinline__ float2 ffma2(float2 a, float2 b, float2 c) {
    float2 d;
    asm("fma.rn.f32x2 %0, %1, %2, %3;"
        : "=l"(reinterpret_cast<unsigned long long&>(d))
        : "l"(reinterpret_cast<unsigned long long&>(a)),
          "l"(reinterpret_cast<unsigned long long&>(b)),
          "l"(reinterpret_cast<unsigned long long&>(c)));
    return d;
}
__device__ __forceinline__ float2 fmul2(float2 a, float2 b) {
    float2 d;
    asm("mul.rn.f32x2 %0, %1, %2;"
        : "=l"(reinterpret_cast<unsigned long long&>(d))
        : "l"(reinterpret_cast<unsigned long long&>(a)),
          "l"(reinterpret_cast<unsigned long long&>(b)));
    return d;
}

// ---- software grid barrier (128 blocks, 1/SM, guaranteed resident) ----
__device__ __forceinline__ void gridbar() {
    __syncthreads();
    if (threadIdx.x == 0) {
        __threadfence();
        int g = g_gen;
        if (atomicAdd(&g_cnt, 1) == GRID - 1) {
            g_cnt = 0;
            __threadfence();
            g_gen = g + 1;
        } else {
            while (g_gen == g) __nanosleep(32);
        }
        __threadfence();
    }
    __syncthreads();
}

__device__ __forceinline__ void unpack_kp(const uint4& v, float2* kp) {
    const __half2* h = (const __half2*)&v;
    kp[0] = __half22float2(h[0]);
    kp[1] = __half22float2(h[1]);
    kp[2] = __half22float2(h[2]);
    kp[3] = __half22float2(h[3]);
}

__global__ void __launch_bounds__(TPB, 1)
k_sinkhorn(const float* __restrict__ C, float* __restrict__ out)
{
    extern __shared__ unsigned char smraw[];
    uint4* sK   = (uint4*)(smraw + OFF_SK);     // [80][128] uint4
    float* sT   = (float*)(smraw + OFF_ST);
    float* sb   = (float*)(smraw + OFF_SB);
    float* sU   = (float*)(smraw + OFF_SU);
    float* sA   = (float*)(smraw + OFF_SA);
    float* sred = (float*)(smraw + OFF_SR);

    const int bid = blockIdx.x;
    const int b   = bid >> 3;
    const int ib  = bid & 7;
    const int tid = threadIdx.x;
    const int w   = tid >> 5;
    const int l   = tid & 31;
    const int rowBase = (b << 10) + (ib << 7);
    const int wrow    = rowBase + w * RPW;

    const float MUA = (1.0f / 1024.0f + 1e-8f) * 4096.0f;  // mu * 4096
    const float UC  = logf(MUA);                           // log(mu) + 12 ln2
    const float KSH = 8.317766166719343f;                  // 12 ln2

    if (tid < 128) { sU[tid] = 0.f; sA[tid] = 0.f; }
    ((float4*)sb)[tid] = make_float4(1.f, 1.f, 1.f, 1.f);  // b0 = 1
    __syncthreads();

    const float4* C4    = (const float4*)C;
    float*        outCost = out;
    float4*       outPi   = (float4*)(out + NB);
    float4*       outC    = (float4*)(out + NB + (size_t)NB * NN * NN);

    int par = 0, copied = 0;
    for (int t = 0; t < 100; t++) {
        // ---- cache b in packed-pair registers ----
        float2 bb[16];
        const float2* sb2 = (const float2*)sb;
        #pragma unroll
        for (int k = 0; k < 4; k++) {
            int q = (k << 5) + l;
            #pragma unroll
            for (int e = 0; e < 4; e++) bb[k * 4 + e] = sb2[4 * q + e];
        }
        float2 Tacc[16];
        #pragma unroll
        for (int i = 0; i < 16; i++) Tacc[i] = make_float2(0.f, 0.f);
        float du = 0.f;

        // per-row worker: dot (f32x2), u/a update, T accumulate (f32x2)
        auto proc = [&](float2* kp, int r) {
            float2 sa = make_float2(0.f, 0.f), sc = make_float2(0.f, 0.f);
            #pragma unroll
            for (int i = 0; i < 16; i += 2) {
                sa = ffma2(kp[i],     bb[i],     sa);
                sc = ffma2(kp[i + 1], bb[i + 1], sc);
            }
            float s = sa.x + sa.y + sc.x + sc.y;
            #pragma unroll
            for (int o = 16; o; o >>= 1) s += __shfl_xor_sync(~0u, s, o);
            float a = MUA / s;
            if (l == 0) {
                float un = 0.1f * (UC - logf(s));
                int ri = w * RPW + r;
                du += fabsf(un - sU[ri]);
                sU[ri] = un; sA[ri] = a;
            }
            float2 a2 = make_float2(a, a);
            #pragma unroll
            for (int i = 0; i < 16; i++) Tacc[i] = ffma2(a2, kp[i], Tacc[i]);
        };

        if (t == 0) {
            // ---- first pass: build fp16 K' = 4096*exp(-C/eps) ----
            #pragma unroll 1
            for (int r = 0; r < RPW; r++) {
                int row = wrow + r;
                float2 kp[16];
                uint4 kv[4];
                #pragma unroll
                for (int k = 0; k < 4; k++) {
                    size_t q = (size_t)row * 256 + (((k << 5) + l) << 1);
                    float4 c0 = C4[q], c1 = C4[q + 1];
                    __half2 h0 = __floats2half2_rn(__expf(fmaf(-10.f, c0.x, KSH)),
                                                   __expf(fmaf(-10.f, c0.y, KSH)));
                    __half2 h1 = __floats2half2_rn(__expf(fmaf(-10.f, c0.z, KSH)),
                                                   __expf(fmaf(-10.f, c0.w, KSH)));
                    __half2 h2 = __floats2half2_rn(__expf(fmaf(-10.f, c1.x, KSH)),
                                                   __expf(fmaf(-10.f, c1.y, KSH)));
                    __half2 h3 = __floats2half2_rn(__expf(fmaf(-10.f, c1.z, KSH)),
                                                   __expf(fmaf(-10.f, c1.w, KSH)));
                    uint4 v;
                    v.x = *(unsigned*)&h0; v.y = *(unsigned*)&h1;
                    v.z = *(unsigned*)&h2; v.w = *(unsigned*)&h3;
                    kv[k] = v;
                    kp[k * 4 + 0] = __half22float2(h0);
                    kp[k * 4 + 1] = __half22float2(h1);
                    kp[k * 4 + 2] = __half22float2(h2);
                    kp[k * 4 + 3] = __half22float2(h3);
                }
                if (r < SROWS_W) {
                    #pragma unroll
                    for (int k = 0; k < 4; k++)
                        sK[(w * SROWS_W + r) * 128 + (k << 5) + l] = kv[k];
                } else {
                    #pragma unroll
                    for (int k = 0; k < 4; k++)
                        g_K4[(size_t)row * 128 + (k << 5) + l] = kv[k];
                }
                proc(kp, r);
            }
        } else {
            // ---- steady state: smem rows, then global rows (prefetched) ----
            uint4 pre[4];
            {
                size_t gq = (size_t)(wrow + SROWS_W) * 128;
                #pragma unroll
                for (int k = 0; k < 4; k++) pre[k] = g_K4[gq + (k << 5) + l];
            }
            #pragma unroll 1
            for (int r = 0; r < SROWS_W; r++) {
                float2 kp[16];
                #pragma unroll
                for (int k = 0; k < 4; k++) {
                    uint4 v = sK[(w * SROWS_W + r) * 128 + (k << 5) + l];
                    unpack_kp(v, &kp[k * 4]);
                }
                proc(kp, r);
            }
            #pragma unroll 1
            for (int r = SROWS_W; r < RPW; r++) {
                uint4 cur[4];
                #pragma unroll
                for (int k = 0; k < 4; k++) cur[k] = pre[k];
                if (r + 1 < RPW) {
                    size_t gq = (size_t)(wrow + r + 1) * 128;
                    #pragma unroll
                    for (int k = 0; k < 4; k++) pre[k] = g_K4[gq + (k << 5) + l];
                }
                float2 kp[16];
                #pragma unroll
                for (int k = 0; k < 4; k++) unpack_kp(cur[k], &kp[k * 4]);
                proc(kp, r);
            }
        }

        // ---- block-combine 8 warps' column partials ----
        {
            float4* me = (float4*)(sT + w * 1024);
            #pragma unroll
            for (int k = 0; k < 4; k++) {
                int q = (k << 5) + l;
                me[2 * q]     = make_float4(Tacc[k*4+0].x, Tacc[k*4+0].y,
                                            Tacc[k*4+1].x, Tacc[k*4+1].y);
                me[2 * q + 1] = make_float4(Tacc[k*4+2].x, Tacc[k*4+2].y,
                                            Tacc[k*4+3].x, Tacc[k*4+3].y);
            }
            if (l == 0) sred[w] = du;
        }
        __syncthreads();
        {
            float4 Tj = ((const float4*)sT)[tid];
            #pragma unroll
            for (int ww = 1; ww < 8; ww++) {
                float4 x = ((const float4*)(sT + ww * 1024))[tid];
                Tj.x += x.x; Tj.y += x.y; Tj.z += x.z; Tj.w += x.w;
            }
            ((float4*)g_part[par][b][ib])[tid] = Tj;
        }
        if (tid == 0) {
            float e = 0.f;
            #pragma unroll
            for (int ww = 0; ww < 8; ww++) e += sred[ww];
            g_errpart[par][bid] = e;
        }

        gridbar();

        // ---- v update: combine 8 block partials (redundant per block) ----
        float4 T = make_float4(0.f, 0.f, 0.f, 0.f);
        #pragma unroll
        for (int kk = 0; kk < PB; kk++) {
            float4 x = __ldcg(((const float4*)g_part[par][b][kk]) + tid);
            T.x += x.x; T.y += x.y; T.z += x.z; T.w += x.w;
        }
        float4 bbn;
        bbn.x = MUA / T.x; bbn.y = MUA / T.y; bbn.z = MUA / T.z; bbn.w = MUA / T.w;

        sred[tid] = (tid < GRID) ? __ldcg(&g_errpart[par][tid]) : 0.f;
        __syncthreads();
        for (int o = 128; o; o >>= 1) {
            if (tid < o) sred[tid] += sred[tid + o];
            __syncthreads();
        }
        float err = sred[0];

        ((float4*)sb)[tid] = bbn;
        __syncthreads();

        // ---- overlapped C -> outC copy (DRAM idle during loop) ----
        if (t >= 1 && copied < 8) {
            size_t base = ((size_t)(rowBase + copied * 16 + (tid >> 4))) * 256 + (tid & 15);
            #pragma unroll
            for (int j = 0; j < 16; j++) {
                float4 v = __ldcs(C4 + base + j * 16);
                __stcs(outC + base + j * 16, v);
            }
            copied++;
        }

        if (err < 0.1f * (float)NB) break;
        par ^= 1;
    }

    // ---- finish any remaining copy chunks ----
    for (; copied < 8; copied++) {
        size_t base = ((size_t)(rowBase + copied * 16 + (tid >> 4))) * 256 + (tid & 15);
        #pragma unroll
        for (int j = 0; j < 16; j++) {
            float4 v = __ldcs(C4 + base + j * 16);
            __stcs(outC + base + j * 16, v);
        }
    }

    // ---- epilogue: pi = a*b*K'/4096, cost via C reconstructed from K' ----
    const float2* sb2 = (const float2*)sb;
    float2 bbf[16];
    #pragma unroll
    for (int k = 0; k < 4; k++) {
        int q = (k << 5) + l;
        #pragma unroll
        for (int e = 0; e < 4; e++) bbf[k * 4 + e] = sb2[4 * q + e];
    }
    const float LN2E = 0.069314718f;   // 0.1 * ln2
    const float CC   = 0.8317766167f;  // 0.1 * 12 ln2
    float2 cacc = make_float2(0.f, 0.f);

    #pragma unroll 1
    for (int r = 0; r < RPW; r++) {
        int row = wrow + r;
        float ap = sA[w * RPW + r] * (1.0f / 4096.0f);
        float2 ap2 = make_float2(ap, ap);
        float2 kp[16];
        if (r < SROWS_W) {
            #pragma unroll
            for (int k = 0; k < 4; k++) {
                uint4 v = sK[(w * SROWS_W + r) * 128 + (k << 5) + l];
                unpack_kp(v, &kp[k * 4]);
            }
        } else {
            #pragma unroll
            for (int k = 0; k < 4; k++) {
                uint4 v = g_K4[(size_t)row * 128 + (k << 5) + l];
                unpack_kp(v, &kp[k * 4]);
            }
        }
        #pragma unroll
        for (int k = 0; k < 4; k++) {
            int q = (k << 5) + l;
            float2 p0 = fmul2(ap2, fmul2(kp[k*4+0], bbf[k*4+0]));
            float2 p1 = fmul2(ap2, fmul2(kp[k*4+1], bbf[k*4+1]));
            float2 p2 = fmul2(ap2, fmul2(kp[k*4+2], bbf[k*4+2]));
            float2 p3 = fmul2(ap2, fmul2(kp[k*4+3], bbf[k*4+3]));
            __stcs(&outPi[(size_t)row * 256 + 2 * q],
                   make_float4(p0.x, p0.y, p1.x, p1.y));
            __stcs(&outPi[(size_t)row * 256 + 2 * q + 1],
                   make_float4(p2.x, p2.y, p3.x, p3.y));
            float2 c0, c1, c2, c3;
            c0.x = fmaf(-LN2E, __log2f(kp[k*4+0].x), CC);
            c0.y = fmaf(-LN2E, __log2f(kp[k*4+0].y), CC);
            c1.x = fmaf(-LN2E, __log2f(kp[k*4+1].x), CC);
            c1.y = fmaf(-LN2E, __log2f(kp[k*4+1].y), CC);
            c2.x = fmaf(-LN2E, __log2f(kp[k*4+2].x), CC);
            c2.y = fmaf(-LN2E, __log2f(kp[k*4+2].y), CC);
            c3.x = fmaf(-LN2E, __log2f(kp[k*4+3].x), CC);
            c3.y = fmaf(-LN2E, __log2f(kp[k*4+3].y), CC);
            cacc = ffma2(p0, c0, cacc);
            cacc = ffma2(p1, c1, cacc);
            cacc = ffma2(p2, c2, cacc);
            cacc = ffma2(p3, c3, cacc);
        }
    }
    float cost = cacc.x + cacc.y;
    __syncthreads();
    sred[tid] = cost;
    __syncthreads();
    for (int o = 128; o; o >>= 1) {
        if (tid < o) sred[tid] += sred[tid + o];
        __syncthreads();
    }
    if (tid == 0) g_costpart[bid] = sred[0];

    gridbar();

    if (bid == 0 && tid < NB) {
        float cs = 0.f;
        #pragma unroll
        for (int kk = 0; kk < PB; kk++)
            cs += __ldcg(&g_costpart[(tid << 3) + kk]);
        outCost[tid] = cs;
    }
}

// ---------------- launch -----------------------------------------------------
extern "C" void kernel_launch(void* const* d_in, const int* in_sizes, int n_in,
                              void* d_out, int out_size) {
    const float* C = nullptr;
    for (int i = 0; i < n_in; i++)
        if (in_sizes[i] == NB * NN * NN) C = (const float*)d_in[i];
    cudaFuncSetAttribute(k_sinkhorn,
                         cudaFuncAttributeMaxDynamicSharedMemorySize, SMEM_TOTAL);
    k_sinkhorn<<<GRID, TPB, SMEM_TOTAL>>>(C, (float*)d_out);
    (void)out_size;
}

// round 10
// speedup vs baseline: 1.3571x; 1.3571x over previous
#include <cuda_runtime.h>
#include <cuda_fp16.h>
#include <math.h>

#define NB   16            // batches
#define NN   1024          // N == Mp
#define GRID 128           // 16 batches x 8 blocks; 1 CTA/SM, all co-resident
#define TPB  256
#define PB   8             // blocks per batch
#define RPW  16            // rows per warp
#define CROWS 9            // rows/warp kept L1-resident (default ld); rest __ldcg

// ---- static device scratch (no allocations allowed) ----
__device__ uint4  g_K4[(size_t)NB * NN * NN / 8];   // fp16 K' = 4096*exp(-C/eps)
__device__ float  g_part[2][NB][PB][NN];
__device__ float  g_errpart[2][GRID];
__device__ float  g_costpart[GRID];
__device__ int          g_cnt;
__device__ volatile int g_gen;

// ---- packed f32x2 helpers (Blackwell FFMA2 — PTX only) ----
__device__ __forceinline__ float2 ffma2(float2 a, float2 b, float2 c) {
    float2 d;
    asm("fma.rn.f32x2 %0, %1, %2, %3;"
        : "=l"(reinterpret_cast<unsigned long long&>(d))
        : "l"(reinterpret_cast<unsigned long long&>(a)),
          "l"(reinterpret_cast<unsigned long long&>(b)),
          "l"(reinterpret_cast<unsigned long long&>(c)));
    return d;
}
__device__ __forceinline__ float2 fmul2(float2 a, float2 b) {
    float2 d;
    asm("mul.rn.f32x2 %0, %1, %2;"
        : "=l"(reinterpret_cast<unsigned long long&>(d))
        : "l"(reinterpret_cast<unsigned long long&>(a)),
          "l"(reinterpret_cast<unsigned long long&>(b)));
    return d;
}

// ---- software grid barrier (128 blocks, 1/SM, guaranteed resident) ----
__device__ __forceinline__ void gridbar() {
    __syncthreads();
    if (threadIdx.x == 0) {
        __threadfence();
        int g = g_gen;
        if (atomicAdd(&g_cnt, 1) == GRID - 1) {
            g_cnt = 0;
            __threadfence();
            g_gen = g + 1;
        } else {
            while (g_gen == g) __nanosleep(32);
        }
        __threadfence();
    }
    __syncthreads();
}

__device__ __forceinline__ void unpack_kp(const uint4& v, float2* kp) {
    const __half2* h = (const __half2*)&v;
    kp[0] = __half22float2(h[0]);
    kp[1] = __half22float2(h[1]);
    kp[2] = __half22float2(h[2]);
    kp[3] = __half22float2(h[3]);
}

__global__ void __launch_bounds__(TPB, 1)
k_sinkhorn(const float* __restrict__ C, float* __restrict__ out)
{
    __shared__ float sT[8][NN];      // 32 KB: per-warp column partials
    __shared__ float sb[NN];         // current b (exp(v/eps)) for this batch
    __shared__ float sU[128];
    __shared__ float sA[128];
    __shared__ float sred[TPB];

    const int bid = blockIdx.x;
    const int b   = bid >> 3;
    const int ib  = bid & 7;
    const int tid = threadIdx.x;
    const int w   = tid >> 5;
    const int l   = tid & 31;
    const int rowBase = (b << 10) + (ib << 7);   // 128 rows per block
    const int wrow    = rowBase + w * RPW;       // this warp's 16 rows

    const float MUA = (1.0f / 1024.0f + 1e-8f) * 4096.0f;  // mu * 4096
    const float UC  = logf(MUA);                           // log(mu) + 12 ln2
    const float KSH = 8.317766166719343f;                  // 12 ln2

    if (tid < 128) { sU[tid] = 0.f; sA[tid] = 0.f; }
    ((float4*)sb)[tid] = make_float4(1.f, 1.f, 1.f, 1.f);  // b0 = 1
    __syncthreads();

    const float4* C4      = (const float4*)C;
    float*        outCost = out;
    float4*       outPi   = (float4*)(out + NB);
    float4*       outC    = (float4*)(out + NB + (size_t)NB * NN * NN);

    int par = 0;
    for (int t = 0; t < 100; t++) {
        // ---- cache b in packed-pair registers ----
        float2 bb[16];
        const float2* sb2 = (const float2*)sb;
        #pragma unroll
        for (int k = 0; k < 4; k++) {
            int q = (k << 5) + l;
            #pragma unroll
            for (int e = 0; e < 4; e++) bb[k * 4 + e] = sb2[4 * q + e];
        }
        float2 Tacc[16];
        #pragma unroll
        for (int i = 0; i < 16; i++) Tacc[i] = make_float2(0.f, 0.f);
        float du = 0.f;

        // per-row worker: f32x2 dot, u/a update, f32x2 T accumulate
        auto proc = [&](float2* kp, int r) {
            float2 sa = make_float2(0.f, 0.f), sc = make_float2(0.f, 0.f);
            #pragma unroll
            for (int i = 0; i < 16; i += 2) {
                sa = ffma2(kp[i],     bb[i],     sa);
                sc = ffma2(kp[i + 1], bb[i + 1], sc);
            }
            float s = sa.x + sa.y + sc.x + sc.y;
            #pragma unroll
            for (int o = 16; o; o >>= 1) s += __shfl_xor_sync(~0u, s, o);
            float a = MUA / s;
            if (l == 0) {
                float un = 0.1f * (UC - logf(s));
                int ri = w * RPW + r;
                du += fabsf(un - sU[ri]);
                sU[ri] = un; sA[ri] = a;
            }
            float2 a2 = make_float2(a, a);
            #pragma unroll
            for (int i = 0; i < 16; i++) Tacc[i] = ffma2(a2, kp[i], Tacc[i]);
        };

        if (t == 0) {
            // ---- first pass: build fp16 K', write outC directly ----
            for (int r = 0; r < RPW; r++) {
                int row = wrow + r;
                size_t q0 = (size_t)row * 256;
                float2 kp[16];
                #pragma unroll
                for (int k = 0; k < 4; k++) {
                    size_t q = q0 + (((k << 5) + l) << 1);
                    float4 c0 = __ldcs(C4 + q);
                    float4 c1 = __ldcs(C4 + q + 1);
                    __stcs(outC + q,     c0);      // C passthrough, fire & forget
                    __stcs(outC + q + 1, c1);
                    __half2 h0 = __floats2half2_rn(__expf(fmaf(-10.f, c0.x, KSH)),
                                                   __expf(fmaf(-10.f, c0.y, KSH)));
                    __half2 h1 = __floats2half2_rn(__expf(fmaf(-10.f, c0.z, KSH)),
                                                   __expf(fmaf(-10.f, c0.w, KSH)));
                    __half2 h2 = __floats2half2_rn(__expf(fmaf(-10.f, c1.x, KSH)),
                                                   __expf(fmaf(-10.f, c1.y, KSH)));
                    __half2 h3 = __floats2half2_rn(__expf(fmaf(-10.f, c1.z, KSH)),
                                                   __expf(fmaf(-10.f, c1.w, KSH)));
                    uint4 v;
                    v.x = *(unsigned*)&h0; v.y = *(unsigned*)&h1;
                    v.z = *(unsigned*)&h2; v.w = *(unsigned*)&h3;
                    __stcg(&g_K4[(size_t)row * 128 + (k << 5) + l], v);
                    kp[k * 4 + 0] = __half22float2(h0);
                    kp[k * 4 + 1] = __half22float2(h1);
                    kp[k * 4 + 2] = __half22float2(h2);
                    kp[k * 4 + 3] = __half22float2(h3);
                }
                proc(kp, r);
            }
        } else {
            // ---- steady state: prefetched, L1-cached/bypass split ----
            uint4 kq[4], kn[4];
            {
                size_t gq = (size_t)wrow * 128;
                #pragma unroll
                for (int k = 0; k < 4; k++)
                    kq[k] = g_K4[gq + (k << 5) + l];          // r=0: cached class
            }
            #pragma unroll
            for (int r = 0; r < RPW; r++) {
                if (r + 1 < RPW) {
                    size_t gq = (size_t)(wrow + r + 1) * 128;
                    if (r + 1 < CROWS) {
                        #pragma unroll
                        for (int k = 0; k < 4; k++)
                            kn[k] = g_K4[gq + (k << 5) + l];  // L1-resident set
                    } else {
                        #pragma unroll
                        for (int k = 0; k < 4; k++)
                            kn[k] = __ldcg(&g_K4[gq + (k << 5) + l]);  // bypass L1
                    }
                }
                float2 kp[16];
                #pragma unroll
                for (int k = 0; k < 4; k++) unpack_kp(kq[k], &kp[k * 4]);
                proc(kp, r);
                if (r + 1 < RPW) {
                    #pragma unroll
                    for (int k = 0; k < 4; k++) kq[k] = kn[k];
                }
            }
        }

        // ---- block-combine 8 warps' column partials (deterministic) ----
        {
            float4* me = (float4*)sT[w];
            #pragma unroll
            for (int k = 0; k < 4; k++) {
                int q = (k << 5) + l;
                me[2 * q]     = make_float4(Tacc[k*4+0].x, Tacc[k*4+0].y,
                                            Tacc[k*4+1].x, Tacc[k*4+1].y);
                me[2 * q + 1] = make_float4(Tacc[k*4+2].x, Tacc[k*4+2].y,
                                            Tacc[k*4+3].x, Tacc[k*4+3].y);
            }
            if (l == 0) sred[w] = du;
        }
        __syncthreads();
        {
            float4 Tj = ((const float4*)sT[0])[tid];
            #pragma unroll
            for (int ww = 1; ww < 8; ww++) {
                float4 x = ((const float4*)sT[ww])[tid];
                Tj.x += x.x; Tj.y += x.y; Tj.z += x.z; Tj.w += x.w;
            }
            ((float4*)g_part[par][b][ib])[tid] = Tj;
        }
        if (tid == 0) {
            float e = 0.f;
            #pragma unroll
            for (int ww = 0; ww < 8; ww++) e += sred[ww];
            g_errpart[par][bid] = e;
        }

        gridbar();

        // ---- v update: combine 8 block partials (redundant per block) ----
        float4 T = make_float4(0.f, 0.f, 0.f, 0.f);
        #pragma unroll
        for (int kk = 0; kk < PB; kk++) {
            float4 x = __ldcg(((const float4*)g_part[par][b][kk]) + tid);
            T.x += x.x; T.y += x.y; T.z += x.z; T.w += x.w;
        }
        float4 bbn;
        bbn.x = MUA / T.x; bbn.y = MUA / T.y; bbn.z = MUA / T.z; bbn.w = MUA / T.w;

        // deterministic err reduction
        sred[tid] = (tid < GRID) ? __ldcg(&g_errpart[par][tid]) : 0.f;
        __syncthreads();
        for (int o = 128; o; o >>= 1) {
            if (tid < o) sred[tid] += sred[tid + o];
            __syncthreads();
        }
        float err = sred[0];

        ((float4*)sb)[tid] = bbn;
        __syncthreads();

        if (err < 0.1f * (float)NB) break;   // err/B < THRESH
        par ^= 1;
    }

    // ---- epilogue: pi = a*b*K'/4096, cost via C reconstructed from K' ----
    const float2* sb2 = (const float2*)sb;
    float2 bbf[16];
    #pragma unroll
    for (int k = 0; k < 4; k++) {
        int q = (k << 5) + l;
        #pragma unroll
        for (int e = 0; e < 4; e++) bbf[k * 4 + e] = sb2[4 * q + e];
    }
    const float LN2E = 0.069314718f;   // 0.1 * ln2
    const float CC   = 0.8317766167f;  // 0.1 * 12 ln2
    float2 cacc = make_float2(0.f, 0.f);

    for (int r = 0; r < RPW; r++) {
        int row = wrow + r;
        float ap = sA[w * RPW + r] * (1.0f / 4096.0f);
        float2 ap2 = make_float2(ap, ap);
        float2 kp[16];
        size_t gq = (size_t)row * 128;
        if (r < CROWS) {
            #pragma unroll
            for (int k = 0; k < 4; k++) {
                uint4 v = g_K4[gq + (k << 5) + l];            // L1 hits from loop
                unpack_kp(v, &kp[k * 4]);
            }
        } else {
            #pragma unroll
            for (int k = 0; k < 4; k++) {
                uint4 v = __ldcg(&g_K4[gq + (k << 5) + l]);
                unpack_kp(v, &kp[k * 4]);
            }
        }
        #pragma unroll
        for (int k = 0; k < 4; k++) {
            int q = (k << 5) + l;
            float2 p0 = fmul2(ap2, fmul2(kp[k*4+0], bbf[k*4+0]));
            float2 p1 = fmul2(ap2, fmul2(kp[k*4+1], bbf[k*4+1]));
            float2 p2 = fmul2(ap2, fmul2(kp[k*4+2], bbf[k*4+2]));
            float2 p3 = fmul2(ap2, fmul2(kp[k*4+3], bbf[k*4+3]));
            __stcs(&outPi[(size_t)row * 256 + 2 * q],
                   make_float4(p0.x, p0.y, p1.x, p1.y));
            __stcs(&outPi[(size_t)row * 256 + 2 * q + 1],
                   make_float4(p2.x, p2.y, p3.x, p3.y));
            float2 c0, c1, c2, c3;
            c0.x = fmaf(-LN2E, __log2f(kp[k*4+0].x), CC);
            c0.y = fmaf(-LN2E, __log2f(kp[k*4+0].y), CC);
            c1.x = fmaf(-LN2E, __log2f(kp[k*4+1].x), CC);
            c1.y = fmaf(-LN2E, __log2f(kp[k*4+1].y), CC);
            c2.x = fmaf(-LN2E, __log2f(kp[k*4+2].x), CC);
            c2.y = fmaf(-LN2E, __log2f(kp[k*4+2].y), CC);
            c3.x = fmaf(-LN2E, __log2f(kp[k*4+3].x), CC);
            c3.y = fmaf(-LN2E, __log2f(kp[k*4+3].y), CC);
            cacc = ffma2(p0, c0, cacc);
            cacc = ffma2(p1, c1, cacc);
            cacc = ffma2(p2, c2, cacc);
            cacc = ffma2(p3, c3, cacc);
        }
    }
    float cost = cacc.x + cacc.y;
    __syncthreads();
    sred[tid] = cost;
    __syncthreads();
    for (int o = 128; o; o >>= 1) {
        if (tid < o) sred[tid] += sred[tid + o];
        __syncthreads();
    }
    if (tid == 0) g_costpart[bid] = sred[0];

    gridbar();

    if (bid == 0 && tid < NB) {               // deterministic final cost sum
        float cs = 0.f;
        #pragma unroll
        for (int kk = 0; kk < PB; kk++)
            cs += __ldcg(&g_costpart[(tid << 3) + kk]);
        outCost[tid] = cs;
    }
}

// ---------------- launch -----------------------------------------------------
extern "C" void kernel_launch(void* const* d_in, const int* in_sizes, int n_in,
                              void* d_out, int out_size) {
    const float* C = nullptr;
    for (int i = 0; i < n_in; i++)
        if (in_sizes[i] == NB * NN * NN) C = (const float*)d_in[i];
    k_sinkhorn<<<GRID, TPB>>>(C, (float*)d_out);
    (void)out_size;
}